// round 11
// baseline (speedup 1.0000x reference)
#include <cuda_runtime.h>
#include <cstdint>
#include <cstddef>

#define SQ 2048
#define DMODEL 2048
#define NH 16
#define DHEAD 128
#define NCH (DMODEL / 32)

#define DPAD 40                  // dense smem stride; 40%32==8 -> conflict-free float2
#define TILE_F (128 * DPAD)      // one 128-row stage
#define DSM_TOT (4 * TILE_F)     // 2 stages x (A+B) = 80 KB
#define QLD 136                  // flash Q/P stride (%32==8, float2 frags)
#define KLD 136                  // flash K-phase stride
#define VLD 132                  // flash V-phase stride (%32==4, scalar frags)

// ---------------- scratch ----------------------------------------------------
__device__ float g_Q[NH * SQ * DHEAD];
__device__ float g_K[NH * SQ * DHEAD];
__device__ float g_V[NH * SQ * DHEAD];
__device__ float g_attn[SQ * DMODEL];

// ---------------- helpers ---------------------------------------------------
__device__ __forceinline__ float f2tf(float f) {
    uint32_t r;
    asm("cvt.rna.tf32.f32 %0, %1;" : "=r"(r) : "f"(f));
    return __uint_as_float(r);
}
__device__ __forceinline__ uint32_t f2tfu(float f) {
    uint32_t r;
    asm("cvt.rna.tf32.f32 %0, %1;" : "=r"(r) : "f"(f));
    return r;
}

__device__ __forceinline__ float fast_tanh(float x) {
    const float e = __expf(2.0f * x);
    return 1.0f - 2.0f / (e + 1.0f);
}

__device__ __forceinline__ uint32_t s2u(const void* p) {
    uint32_t a;
    asm("{ .reg .u64 t; cvta.to.shared.u64 t, %1; cvt.u32.u64 %0, t; }"
        : "=r"(a) : "l"(p));
    return a;
}

__device__ __forceinline__ void cp16(uint32_t s, const void* g) {
    asm volatile("cp.async.ca.shared.global [%0], [%1], 16;" :: "r"(s), "l"(g) : "memory");
}
__device__ __forceinline__ void cp_commit() {
    asm volatile("cp.async.commit_group;" ::: "memory");
}
template <int N>
__device__ __forceinline__ void cp_wait() {
    asm volatile("cp.async.wait_group %0;" :: "n"(N) : "memory");
}

__device__ __forceinline__ void mma_tf32(float acc[4], const uint32_t a[4],
                                         uint32_t b0, uint32_t b1) {
    asm volatile(
        "mma.sync.aligned.m16n8k8.row.col.f32.tf32.tf32.f32 "
        "{%0,%1,%2,%3}, {%4,%5,%6,%7}, {%8,%9}, {%0,%1,%2,%3};\n"
        : "+f"(acc[0]), "+f"(acc[1]), "+f"(acc[2]), "+f"(acc[3])
        : "r"(a[0]), "r"(a[1]), "r"(a[2]), "r"(a[3]), "r"(b0), "r"(b1));
}

__device__ __forceinline__ int acc_row8(int wm, int mt, int g, int i) {
    return wm * 32 + mt * 16 + g + ((i >> 1) << 3);
}
__device__ __forceinline__ int acc_col8(int wn, int nt, int c, int i) {
    return wn * 64 + nt * 8 + c * 2 + (i & 1);
}

// ---------------- dense GEMM core: 128x128 CTA, warp 32x64, 2 CTAs/SM -------
// cvt-in-frag; A-frags pipelined across kk; B-frags inline (latency covered
// by 4 warps/SMSP). k-permutation identical on A and B.
__device__ __forceinline__ void gemm128(const float* __restrict__ A, int lda,
                                        const float* __restrict__ B, int ldb,
                                        float acc[2][8][4], float* sm) {
    const int tid = threadIdx.x, warp = tid >> 5, lane = tid & 31;
    const int wm = warp >> 1, wn = warp & 1, g = lane >> 2, c = lane & 3;
    const int r = tid >> 3, c4 = (tid & 7) << 2;
    const uint32_t sb = s2u(sm);

    auto stage = [&](int buf, int k0) {
        const uint32_t abase = sb + (buf ? TILE_F : 0) * 4;
        const uint32_t bbase = sb + ((2 + buf) * TILE_F) * 4;
        #pragma unroll
        for (int s = 0; s < 4; s++) {
            const int row = r + s * 32;
            cp16(abase + (row * DPAD + c4) * 4, &A[(size_t)row * lda + k0 + c4]);
            cp16(bbase + (row * DPAD + c4) * 4, &B[(size_t)row * ldb + k0 + c4]);
        }
    };

    stage(0, 0);
    cp_commit();

    for (int ch = 0; ch < NCH; ch++) {
        const int buf = ch & 1;
        if (ch + 1 < NCH) {
            stage(buf ^ 1, (ch + 1) * 32);
            cp_commit();
            cp_wait<1>();
        } else {
            cp_wait<0>();
        }
        __syncthreads();

        const float* Ab = sm + (buf ? TILE_F : 0);
        const float* Bb = sm + (2 + buf) * TILE_F;

        uint32_t afb[2][2][4];
        auto ldA = [&](int kk, int fb) {
            #pragma unroll
            for (int mt = 0; mt < 2; mt++) {
                const int m0 = wm * 32 + mt * 16 + g;
                const float2 p0 = *reinterpret_cast<const float2*>(&Ab[m0 * DPAD + kk + 2 * c]);
                const float2 p1 = *reinterpret_cast<const float2*>(&Ab[(m0 + 8) * DPAD + kk + 2 * c]);
                afb[fb][mt][0] = f2tfu(p0.x); afb[fb][mt][2] = f2tfu(p0.y);
                afb[fb][mt][1] = f2tfu(p1.x); afb[fb][mt][3] = f2tfu(p1.y);
            }
        };

        ldA(0, 0);
        #pragma unroll
        for (int ks = 0; ks < 4; ks++) {
            const int cur = ks & 1;
            if (ks < 3) ldA((ks + 1) * 8, cur ^ 1);
            const int kk = ks * 8;
            #pragma unroll
            for (int nt = 0; nt < 8; nt++) {
                const float2 bb = *reinterpret_cast<const float2*>(
                    &Bb[(wn * 64 + nt * 8 + g) * DPAD + kk + 2 * c]);
                const uint32_t b0 = f2tfu(bb.x);
                const uint32_t b1 = f2tfu(bb.y);
                #pragma unroll
                for (int mt = 0; mt < 2; mt++)
                    mma_tf32(acc[mt][nt], afb[cur][mt], b0, b1);
            }
        }
        __syncthreads();
    }
}

// ---------------- kernel 1: QKV projections --------------------------------
__global__ __launch_bounds__(256, 2) void qkv_kernel(const float* __restrict__ x,
                                                     const float* __restrict__ wq,
                                                     const float* __restrict__ wk,
                                                     const float* __restrict__ wv) {
    extern __shared__ float dsm[];
    const int which = blockIdx.z;
    const float* W = (which == 0) ? wq : (which == 1) ? wk : wv;
    float* out = (which == 0) ? g_Q : (which == 1) ? g_K : g_V;

    const int rb = blockIdx.x * 128;
    const int cb = blockIdx.y * 128;
    float acc[2][8][4] = {};
    gemm128(x + (size_t)rb * DMODEL, DMODEL,
            W + (size_t)cb * DMODEL, DMODEL, acc, dsm);

    const int tid = threadIdx.x, warp = tid >> 5, lane = tid & 31;
    const int wm = warp >> 1, wn = warp & 1, g = lane >> 2, c = lane & 3;
    const bool roundV = (which == 2);
    #pragma unroll
    for (int mt = 0; mt < 2; mt++)
        #pragma unroll
        for (int nt = 0; nt < 8; nt++)
            #pragma unroll
            for (int i = 0; i < 4; i++) {
                const int s = rb + acc_row8(wm, mt, g, i);
                const int p = cb + acc_col8(wn, nt, c, i);
                const int h = p >> 7, dh = p & 127;
                const float v = roundV ? f2tf(acc[mt][nt][i]) : acc[mt][nt][i];
                out[(size_t)h * SQ * DHEAD + (size_t)s * DHEAD + dh] = v;
            }
}

// ---------------- kernel 2: RoPE in-place, stores tf32-exact ----------------
__global__ void rope_kernel(const float* __restrict__ cosb,
                            const float* __restrict__ sinb) {
    const int t = blockIdx.x * blockDim.x + threadIdx.x;
    const int d  = t & 63;
    const int s  = (t >> 6) & (SQ - 1);
    const int h  = (t >> 17) & (NH - 1);
    const int qk = t >> 21;
    float* p = (qk ? g_K : g_Q) + (size_t)h * SQ * DHEAD + (size_t)s * DHEAD;
    const float x0 = p[d], x1 = p[d + 64];
    const float c0 = cosb[s * DHEAD + d],      s0 = sinb[s * DHEAD + d];
    const float c1 = cosb[s * DHEAD + d + 64], s1 = sinb[s * DHEAD + d + 64];
    p[d]      = f2tf(x0 * c0 - x1 * s0);
    p[d + 64] = f2tf(x1 * c1 + x0 * s1);
}

// ---------------- kernel 3: flash attention, full-tile K/V staging ----------
#define FL_QS 0
#define FL_PS (128 * QLD)
#define FL_KV (2 * 128 * QLD)
#define FL_M  (FL_KV + 128 * KLD)
#define FL_L  (FL_M + 128)
#define FL_RMAX (FL_L + 128)
#define FL_RSUM (FL_RMAX + 256)
#define FL_TOT  (FL_RSUM + 256)

__global__ __launch_bounds__(256) void flash_kernel() {
    extern __shared__ float sm[];
    float* Qs = sm + FL_QS;
    float* Ps = sm + FL_PS;
    float* KV = sm + FL_KV;
    float* m_state = sm + FL_M;
    float* l_state = sm + FL_L;
    float* rmax = sm + FL_RMAX;
    float* rsum = sm + FL_RSUM;
    const uint32_t kvb = s2u(KV);

    const int bid = blockIdx.x;
    const int qt  = 15 - (bid >> 4);
    const int h   = bid & 15;
    const int rb  = qt * 128;

    const int tid = threadIdx.x, warp = tid >> 5, lane = tid & 31;
    const int wm = warp >> 1, wn = warp & 1, g = lane >> 2, c = lane & 3;
    const int m0b = wm * 32;
    const int r = tid >> 3, c4 = (tid & 7) << 2;

    if (tid < 128) { m_state[tid] = -1e30f; l_state[tid] = 0.f; }

    {
        const float* Qg = g_Q + (size_t)h * SQ * DHEAD + (size_t)rb * DHEAD;
        #pragma unroll
        for (int s = 0; s < 4; s++)
            #pragma unroll
            for (int cc = 0; cc < 4; cc++) {
                const int row = r + s * 32, col = c4 + cc * 32;
                *reinterpret_cast<float4*>(&Qs[row * QLD + col]) =
                    *reinterpret_cast<const float4*>(&Qg[(size_t)row * DHEAD + col]);
            }
    }

    float acc_o[2][8][4] = {};

    for (int kt = 0; kt <= qt; kt++) {
        const int cb = kt * 128;
        const float* Kg = g_K + (size_t)h * SQ * DHEAD + (size_t)cb * DHEAD;
        const float* Vg = g_V + (size_t)h * SQ * DHEAD + (size_t)cb * DHEAD;
        float acc[2][8][4] = {};

        __syncthreads();
        #pragma unroll
        for (int s = 0; s < 16; s++) {
            const int idx = s * 256 + tid;
            const int row = idx >> 5;
            const int cf  = (idx & 31) << 2;
            cp16(kvb + (row * KLD + cf) * 4, &Kg[(size_t)row * DHEAD + cf]);
        }
        cp_commit();
        cp_wait<0>();
        __syncthreads();

        #pragma unroll
        for (int kk = 0; kk < 128; kk += 8) {
            uint32_t af[2][4];
            #pragma unroll
            for (int mt = 0; mt < 2; mt++) {
                const int m0 = m0b + mt * 16 + g;
                const float2 q0 = *reinterpret_cast<const float2*>(&Qs[m0 * QLD + kk + 2 * c]);
                const float2 q1 = *reinterpret_cast<const float2*>(&Qs[(m0 + 8) * QLD + kk + 2 * c]);
                af[mt][0] = __float_as_uint(q0.x); af[mt][2] = __float_as_uint(q0.y);
                af[mt][1] = __float_as_uint(q1.x); af[mt][3] = __float_as_uint(q1.y);
            }
            #pragma unroll
            for (int nt = 0; nt < 8; nt++) {
                const float2 bb = *reinterpret_cast<const float2*>(
                    &KV[(wn * 64 + nt * 8 + g) * KLD + kk + 2 * c]);
                const uint32_t b0 = __float_as_uint(bb.x);
                const uint32_t b1 = __float_as_uint(bb.y);
                #pragma unroll
                for (int mt = 0; mt < 2; mt++)
                    mma_tf32(acc[mt][nt], af[mt], b0, b1);
            }
        }

        float pmax[2][2] = {{-1e30f, -1e30f}, {-1e30f, -1e30f}};
        #pragma unroll
        for (int mt = 0; mt < 2; mt++)
            #pragma unroll
            for (int nt = 0; nt < 8; nt++)
                #pragma unroll
                for (int i = 0; i < 4; i++) {
                    float v = acc[mt][nt][i] * 0.08838834764831845f;
                    v = fast_tanh(v * 0.02f) * 50.0f;
                    if (kt == qt) {
                        const int rr = acc_row8(wm, mt, g, i);
                        const int cl = acc_col8(wn, nt, c, i);
                        if (cl > rr) v = -1e30f;
                    }
                    acc[mt][nt][i] = v;
                    pmax[mt][i >> 1] = fmaxf(pmax[mt][i >> 1], v);
                }
        #pragma unroll
        for (int mt = 0; mt < 2; mt++)
            #pragma unroll
            for (int rh = 0; rh < 2; rh++) {
                float p = pmax[mt][rh];
                p = fmaxf(p, __shfl_xor_sync(0xffffffffu, p, 1));
                p = fmaxf(p, __shfl_xor_sync(0xffffffffu, p, 2));
                pmax[mt][rh] = p;
            }
        if (c == 0) {
            #pragma unroll
            for (int mt = 0; mt < 2; mt++)
                #pragma unroll
                for (int rh = 0; rh < 2; rh++)
                    rmax[wn * 128 + m0b + mt * 16 + rh * 8 + g] = pmax[mt][rh];
        }
        __syncthreads();

        float mnew[2][2], scal[2][2], psum[2][2] = {};
        #pragma unroll
        for (int mt = 0; mt < 2; mt++)
            #pragma unroll
            for (int rh = 0; rh < 2; rh++) {
                const int rr = m0b + mt * 16 + rh * 8 + g;
                const float mo = m_state[rr];
                const float tm = fmaxf(rmax[rr], rmax[128 + rr]);
                const float mn = fmaxf(mo, tm);
                mnew[mt][rh] = mn;
                scal[mt][rh] = __expf(mo - mn);
            }
        #pragma unroll
        for (int mt = 0; mt < 2; mt++)
            #pragma unroll
            for (int nt = 0; nt < 8; nt++)
                #pragma unroll
                for (int i = 0; i < 4; i++) {
                    const int rr = acc_row8(wm, mt, g, i);
                    const int cl = acc_col8(wn, nt, c, i);
                    const float p = __expf(acc[mt][nt][i] - mnew[mt][i >> 1]);
                    psum[mt][i >> 1] += p;
                    Ps[rr * QLD + cl] = f2tf(p);
                }
        #pragma unroll
        for (int mt = 0; mt < 2; mt++)
            #pragma unroll
            for (int rh = 0; rh < 2; rh++) {
                float p = psum[mt][rh];
                p += __shfl_xor_sync(0xffffffffu, p, 1);
                p += __shfl_xor_sync(0xffffffffu, p, 2);
                psum[mt][rh] = p;
            }
        if (c == 0) {
            #pragma unroll
            for (int mt = 0; mt < 2; mt++)
                #pragma unroll
                for (int rh = 0; rh < 2; rh++)
                    rsum[wn * 128 + m0b + mt * 16 + rh * 8 + g] = psum[mt][rh];
        }
        __syncthreads();

        if (wn == 0 && c == 0) {
            #pragma unroll
            for (int mt = 0; mt < 2; mt++)
                #pragma unroll
                for (int rh = 0; rh < 2; rh++) {
                    const int rr = m0b + mt * 16 + rh * 8 + g;
                    l_state[rr] = l_state[rr] * scal[mt][rh] + rsum[rr] + rsum[128 + rr];
                    m_state[rr] = mnew[mt][rh];
                }
        }
        #pragma unroll
        for (int mt = 0; mt < 2; mt++)
            #pragma unroll
            for (int nt = 0; nt < 8; nt++)
                #pragma unroll
                for (int i = 0; i < 4; i++)
                    acc_o[mt][nt][i] *= scal[mt][i >> 1];

        #pragma unroll
        for (int s = 0; s < 16; s++) {
            const int idx = s * 256 + tid;
            const int row = idx >> 5;
            const int cf  = (idx & 31) << 2;
            cp16(kvb + (row * VLD + cf) * 4, &Vg[(size_t)row * DHEAD + cf]);
        }
        cp_commit();
        cp_wait<0>();
        __syncthreads();

        #pragma unroll
        for (int kk = 0; kk < 128; kk += 8) {
            uint32_t af[2][4];
            #pragma unroll
            for (int mt = 0; mt < 2; mt++) {
                const int m0 = m0b + mt * 16 + g;
                const float2 p0 = *reinterpret_cast<const float2*>(&Ps[m0 * QLD + kk + 2 * c]);
                const float2 p1 = *reinterpret_cast<const float2*>(&Ps[(m0 + 8) * QLD + kk + 2 * c]);
                af[mt][0] = __float_as_uint(p0.x); af[mt][2] = __float_as_uint(p0.y);
                af[mt][1] = __float_as_uint(p1.x); af[mt][3] = __float_as_uint(p1.y);
            }
            #pragma unroll
            for (int nt = 0; nt < 8; nt++) {
                const int n0 = wn * 64 + nt * 8 + g;
                const uint32_t b0 = __float_as_uint(KV[(kk + 2 * c) * VLD + n0]);
                const uint32_t b1 = __float_as_uint(KV[(kk + 2 * c + 1) * VLD + n0]);
                #pragma unroll
                for (int mt = 0; mt < 2; mt++)
                    mma_tf32(acc_o[mt][nt], af[mt], b0, b1);
            }
        }
    }

    float inv[2][2];
    #pragma unroll
    for (int mt = 0; mt < 2; mt++)
        #pragma unroll
        for (int rh = 0; rh < 2; rh++)
            inv[mt][rh] = 1.0f / l_state[m0b + mt * 16 + rh * 8 + g];
    #pragma unroll
    for (int mt = 0; mt < 2; mt++)
        #pragma unroll
        for (int nt = 0; nt < 8; nt++)
            #pragma unroll
            for (int i = 0; i < 4; i++) {
                const int q  = rb + acc_row8(wm, mt, g, i);
                const int dh = acc_col8(wn, nt, c, i);
                g_attn[(size_t)q * DMODEL + h * DHEAD + dh] =
                    f2tf(acc_o[mt][nt][i] * inv[mt][i >> 1]);
            }
}

// ---------------- kernel 4: output projection -------------------------------
__global__ __launch_bounds__(256, 2) void oproj_kernel(const float* __restrict__ wo,
                                                       float* __restrict__ out) {
    extern __shared__ float dsm[];
    const int rb = blockIdx.x * 128, cb = blockIdx.y * 128;
    float acc[2][8][4] = {};
    gemm128(g_attn + (size_t)rb * DMODEL, DMODEL,
            wo + (size_t)cb * DMODEL, DMODEL, acc, dsm);

    const int tid = threadIdx.x, warp = tid >> 5, lane = tid & 31;
    const int wm = warp >> 1, wn = warp & 1, g = lane >> 2, c = lane & 3;
    #pragma unroll
    for (int mt = 0; mt < 2; mt++)
        #pragma unroll
        for (int nt = 0; nt < 8; nt++)
            #pragma unroll
            for (int i = 0; i < 4; i++) {
                const int s = rb + acc_row8(wm, mt, g, i);
                const int d = cb + acc_col8(wn, nt, c, i);
                out[(size_t)s * DMODEL + d] = acc[mt][nt][i];
            }
}

// ---------------- launch ----------------------------------------------------
extern "C" void kernel_launch(void* const* d_in, const int* in_sizes, int n_in,
                              void* d_out, int out_size) {
    (void)in_sizes; (void)n_in; (void)out_size;
    const float* x  = (const float*)d_in[0];
    const float* rc = (const float*)d_in[1];
    const float* rs = (const float*)d_in[2];
    const float* wq = (const float*)d_in[4];
    const float* wk = (const float*)d_in[5];
    const float* wv = (const float*)d_in[6];
    const float* wo = (const float*)d_in[7];
    float* out = (float*)d_out;

    const int dense_smem = DSM_TOT * (int)sizeof(float);   // 80 KB
    const int flash_smem = FL_TOT * (int)sizeof(float);    // ~212 KB
    cudaFuncSetAttribute(flash_kernel,
                         cudaFuncAttributeMaxDynamicSharedMemorySize, flash_smem);
    cudaFuncSetAttribute(qkv_kernel,
                         cudaFuncAttributeMaxDynamicSharedMemorySize, dense_smem);
    cudaFuncSetAttribute(oproj_kernel,
                         cudaFuncAttributeMaxDynamicSharedMemorySize, dense_smem);

    qkv_kernel<<<dim3(16, 16, 3), 256, dense_smem>>>(x, wq, wk, wv);
    rope_kernel<<<16384, 256>>>(rc, rs);
    flash_kernel<<<256, 256, flash_smem>>>();
    oproj_kernel<<<dim3(16, 16), 256, dense_smem>>>(wo, out);
}

// round 12
// speedup vs baseline: 1.0325x; 1.0325x over previous
#include <cuda_runtime.h>
#include <cstdint>
#include <cstddef>

#define SQ 2048
#define DMODEL 2048
#define NH 16
#define DHEAD 128
#define NCH (DMODEL / 32)

#define DPAD 40                  // dense smem stride; 40%32==8 -> conflict-free float2
#define AROWS 256
#define BROWS 128
#define ATILE_F (AROWS * DPAD)
#define BTILE_F (BROWS * DPAD)
#define STAGE_F (ATILE_F + BTILE_F)          // 15360 floats per stage
#define DSM_TOT (3 * STAGE_F)                // 3-stage ring = 184320 B
#define QLD 136                  // flash Q/P stride (%32==8, float2 frags)
#define KLD 136                  // flash K-phase stride
#define VLD 132                  // flash V-phase stride (%32==4, scalar frags)

// ---------------- scratch ----------------------------------------------------
__device__ float g_Q[NH * SQ * DHEAD];
__device__ float g_K[NH * SQ * DHEAD];
__device__ float g_V[NH * SQ * DHEAD];
__device__ float g_attn[SQ * DMODEL];

// ---------------- helpers ---------------------------------------------------
__device__ __forceinline__ float f2tf(float f) {
    uint32_t r;
    asm("cvt.rna.tf32.f32 %0, %1;" : "=r"(r) : "f"(f));
    return __uint_as_float(r);
}
__device__ __forceinline__ uint32_t f2tfu(float f) {
    uint32_t r;
    asm("cvt.rna.tf32.f32 %0, %1;" : "=r"(r) : "f"(f));
    return r;
}

__device__ __forceinline__ float fast_tanh(float x) {
    const float e = __expf(2.0f * x);
    return 1.0f - 2.0f / (e + 1.0f);
}

__device__ __forceinline__ uint32_t s2u(const void* p) {
    uint32_t a;
    asm("{ .reg .u64 t; cvta.to.shared.u64 t, %1; cvt.u32.u64 %0, t; }"
        : "=r"(a) : "l"(p));
    return a;
}

__device__ __forceinline__ void cp16(uint32_t s, const void* g) {
    asm volatile("cp.async.ca.shared.global [%0], [%1], 16;" :: "r"(s), "l"(g) : "memory");
}
__device__ __forceinline__ void cp_commit() {
    asm volatile("cp.async.commit_group;" ::: "memory");
}
template <int N>
__device__ __forceinline__ void cp_wait() {
    asm volatile("cp.async.wait_group %0;" :: "n"(N) : "memory");
}

__device__ __forceinline__ void mma_tf32(float acc[4], const uint32_t a[4],
                                         uint32_t b0, uint32_t b1) {
    asm volatile(
        "mma.sync.aligned.m16n8k8.row.col.f32.tf32.tf32.f32 "
        "{%0,%1,%2,%3}, {%4,%5,%6,%7}, {%8,%9}, {%0,%1,%2,%3};\n"
        : "+f"(acc[0]), "+f"(acc[1]), "+f"(acc[2]), "+f"(acc[3])
        : "r"(a[0]), "r"(a[1]), "r"(a[2]), "r"(a[3]), "r"(b0), "r"(b1));
}

__device__ __forceinline__ int acc_row8(int wm, int mt, int g, int i) {
    return wm * 32 + mt * 16 + g + ((i >> 1) << 3);
}
__device__ __forceinline__ int acc_col8(int wn, int nt, int c, int i) {
    return wn * 64 + nt * 8 + c * 2 + (i & 1);
}

// ---------------- dense GEMM core: 256x128 CTA, warp 64x64, 3-stage ring ----
// cvt-in-frag; A/B frags double-buffered across kk; k-permutation identical
// on A and B (slot c <- kk+2c, slot c+4 <- kk+2c+1).
__device__ __forceinline__ void gemm256(const float* __restrict__ A, int lda,
                                        const float* __restrict__ B, int ldb,
                                        float acc[4][8][4], float* sm) {
    const int tid = threadIdx.x, warp = tid >> 5, lane = tid & 31;
    const int wm = warp >> 1, wn = warp & 1, g = lane >> 2, c = lane & 3;
    const int r = tid >> 3, c4 = (tid & 7) << 2;
    const uint32_t sb = s2u(sm);

    auto stage = [&](int s3, int k0) {
        const uint32_t abase = sb + (uint32_t)(s3 * STAGE_F) * 4;
        const uint32_t bbase = abase + (uint32_t)ATILE_F * 4;
        #pragma unroll
        for (int s = 0; s < 8; s++) {
            const int row = r + s * 32;
            cp16(abase + (row * DPAD + c4) * 4, &A[(size_t)row * lda + k0 + c4]);
        }
        #pragma unroll
        for (int s = 0; s < 4; s++) {
            const int row = r + s * 32;
            cp16(bbase + (row * DPAD + c4) * 4, &B[(size_t)row * ldb + k0 + c4]);
        }
    };

    stage(0, 0);  cp_commit();
    stage(1, 32); cp_commit();

    int buf = 0;
    for (int ch = 0; ch < NCH; ch++) {
        if (ch + 2 < NCH) {
            int nb = buf + 2; if (nb >= 3) nb -= 3;
            stage(nb, (ch + 2) * 32);
            cp_commit();
            cp_wait<2>();
        } else if (ch + 1 < NCH) {
            cp_wait<1>();
        } else {
            cp_wait<0>();
        }
        __syncthreads();

        const float* Ab = sm + buf * STAGE_F;
        const float* Bb = Ab + ATILE_F;

        uint32_t afb[2][4][4];
        uint32_t bfb[2][8][2];

        auto ldfrag = [&](int kk, int fb) {
            #pragma unroll
            for (int mt = 0; mt < 4; mt++) {
                const int m0 = wm * 64 + mt * 16 + g;
                const float2 p0 = *reinterpret_cast<const float2*>(&Ab[m0 * DPAD + kk + 2 * c]);
                const float2 p1 = *reinterpret_cast<const float2*>(&Ab[(m0 + 8) * DPAD + kk + 2 * c]);
                afb[fb][mt][0] = f2tfu(p0.x); afb[fb][mt][2] = f2tfu(p0.y);
                afb[fb][mt][1] = f2tfu(p1.x); afb[fb][mt][3] = f2tfu(p1.y);
            }
            #pragma unroll
            for (int nt = 0; nt < 8; nt++) {
                const float2 bb = *reinterpret_cast<const float2*>(
                    &Bb[(wn * 64 + nt * 8 + g) * DPAD + kk + 2 * c]);
                bfb[fb][nt][0] = f2tfu(bb.x);
                bfb[fb][nt][1] = f2tfu(bb.y);
            }
        };

        ldfrag(0, 0);
        #pragma unroll
        for (int ks = 0; ks < 4; ks++) {
            const int cur = ks & 1;
            if (ks < 3) ldfrag((ks + 1) * 8, cur ^ 1);
            #pragma unroll
            for (int nt = 0; nt < 8; nt++)
                #pragma unroll
                for (int mt = 0; mt < 4; mt++)
                    mma_tf32(acc[mt][nt], afb[cur][mt], bfb[cur][nt][0], bfb[cur][nt][1]);
        }
        __syncthreads();   // protect buffer reuse (re-staged 3 chunks later)

        if (++buf == 3) buf = 0;
    }
}

// ---------------- kernel 1: QKV projections --------------------------------
__global__ __launch_bounds__(256, 1) void qkv_kernel(const float* __restrict__ x,
                                                     const float* __restrict__ wq,
                                                     const float* __restrict__ wk,
                                                     const float* __restrict__ wv) {
    extern __shared__ float dsm[];
    const int which = blockIdx.z;
    const float* W = (which == 0) ? wq : (which == 1) ? wk : wv;
    float* out = (which == 0) ? g_Q : (which == 1) ? g_K : g_V;

    const int rb = blockIdx.x * 256;
    const int cb = blockIdx.y * 128;
    float acc[4][8][4] = {};
    gemm256(x + (size_t)rb * DMODEL, DMODEL,
            W + (size_t)cb * DMODEL, DMODEL, acc, dsm);

    const int tid = threadIdx.x, warp = tid >> 5, lane = tid & 31;
    const int wm = warp >> 1, wn = warp & 1, g = lane >> 2, c = lane & 3;
    const bool roundV = (which == 2);
    #pragma unroll
    for (int mt = 0; mt < 4; mt++)
        #pragma unroll
        for (int nt = 0; nt < 8; nt++)
            #pragma unroll
            for (int i = 0; i < 4; i++) {
                const int s = rb + wm * 64 + mt * 16 + g + ((i >> 1) << 3);
                const int p = cb + wn * 64 + nt * 8 + c * 2 + (i & 1);
                const int h = p >> 7, dh = p & 127;
                const float v = roundV ? f2tf(acc[mt][nt][i]) : acc[mt][nt][i];
                out[(size_t)h * SQ * DHEAD + (size_t)s * DHEAD + dh] = v;
            }
}

// ---------------- kernel 2: RoPE in-place, stores tf32-exact ----------------
__global__ void rope_kernel(const float* __restrict__ cosb,
                            const float* __restrict__ sinb) {
    const int t = blockIdx.x * blockDim.x + threadIdx.x;
    const int d  = t & 63;
    const int s  = (t >> 6) & (SQ - 1);
    const int h  = (t >> 17) & (NH - 1);
    const int qk = t >> 21;
    float* p = (qk ? g_K : g_Q) + (size_t)h * SQ * DHEAD + (size_t)s * DHEAD;
    const float x0 = p[d], x1 = p[d + 64];
    const float c0 = cosb[s * DHEAD + d],      s0 = sinb[s * DHEAD + d];
    const float c1 = cosb[s * DHEAD + d + 64], s1 = sinb[s * DHEAD + d + 64];
    p[d]      = f2tf(x0 * c0 - x1 * s0);
    p[d + 64] = f2tf(x1 * c1 + x0 * s1);
}

// ---------------- kernel 3: flash attention, full-tile K/V staging ----------
#define FL_QS 0
#define FL_PS (128 * QLD)
#define FL_KV (2 * 128 * QLD)
#define FL_M  (FL_KV + 128 * KLD)
#define FL_L  (FL_M + 128)
#define FL_RMAX (FL_L + 128)
#define FL_RSUM (FL_RMAX + 256)
#define FL_TOT  (FL_RSUM + 256)

__global__ __launch_bounds__(256) void flash_kernel() {
    extern __shared__ float sm[];
    float* Qs = sm + FL_QS;
    float* Ps = sm + FL_PS;
    float* KV = sm + FL_KV;
    float* m_state = sm + FL_M;
    float* l_state = sm + FL_L;
    float* rmax = sm + FL_RMAX;
    float* rsum = sm + FL_RSUM;
    const uint32_t kvb = s2u(KV);

    const int bid = blockIdx.x;
    const int qt  = 15 - (bid >> 4);
    const int h   = bid & 15;
    const int rb  = qt * 128;

    const int tid = threadIdx.x, warp = tid >> 5, lane = tid & 31;
    const int wm = warp >> 1, wn = warp & 1, g = lane >> 2, c = lane & 3;
    const int m0b = wm * 32;
    const int r = tid >> 3, c4 = (tid & 7) << 2;

    if (tid < 128) { m_state[tid] = -1e30f; l_state[tid] = 0.f; }

    {
        const float* Qg = g_Q + (size_t)h * SQ * DHEAD + (size_t)rb * DHEAD;
        #pragma unroll
        for (int s = 0; s < 4; s++)
            #pragma unroll
            for (int cc = 0; cc < 4; cc++) {
                const int row = r + s * 32, col = c4 + cc * 32;
                *reinterpret_cast<float4*>(&Qs[row * QLD + col]) =
                    *reinterpret_cast<const float4*>(&Qg[(size_t)row * DHEAD + col]);
            }
    }

    float acc_o[2][8][4] = {};

    for (int kt = 0; kt <= qt; kt++) {
        const int cb = kt * 128;
        const float* Kg = g_K + (size_t)h * SQ * DHEAD + (size_t)cb * DHEAD;
        const float* Vg = g_V + (size_t)h * SQ * DHEAD + (size_t)cb * DHEAD;
        float acc[2][8][4] = {};

        __syncthreads();
        #pragma unroll
        for (int s = 0; s < 16; s++) {
            const int idx = s * 256 + tid;
            const int row = idx >> 5;
            const int cf  = (idx & 31) << 2;
            cp16(kvb + (row * KLD + cf) * 4, &Kg[(size_t)row * DHEAD + cf]);
        }
        cp_commit();
        cp_wait<0>();
        __syncthreads();

        #pragma unroll
        for (int kk = 0; kk < 128; kk += 8) {
            uint32_t af[2][4];
            #pragma unroll
            for (int mt = 0; mt < 2; mt++) {
                const int m0 = m0b + mt * 16 + g;
                const float2 q0 = *reinterpret_cast<const float2*>(&Qs[m0 * QLD + kk + 2 * c]);
                const float2 q1 = *reinterpret_cast<const float2*>(&Qs[(m0 + 8) * QLD + kk + 2 * c]);
                af[mt][0] = __float_as_uint(q0.x); af[mt][2] = __float_as_uint(q0.y);
                af[mt][1] = __float_as_uint(q1.x); af[mt][3] = __float_as_uint(q1.y);
            }
            #pragma unroll
            for (int nt = 0; nt < 8; nt++) {
                const float2 bb = *reinterpret_cast<const float2*>(
                    &KV[(wn * 64 + nt * 8 + g) * KLD + kk + 2 * c]);
                const uint32_t b0 = __float_as_uint(bb.x);
                const uint32_t b1 = __float_as_uint(bb.y);
                #pragma unroll
                for (int mt = 0; mt < 2; mt++)
                    mma_tf32(acc[mt][nt], af[mt], b0, b1);
            }
        }

        float pmax[2][2] = {{-1e30f, -1e30f}, {-1e30f, -1e30f}};
        #pragma unroll
        for (int mt = 0; mt < 2; mt++)
            #pragma unroll
            for (int nt = 0; nt < 8; nt++)
                #pragma unroll
                for (int i = 0; i < 4; i++) {
                    float v = acc[mt][nt][i] * 0.08838834764831845f;
                    v = fast_tanh(v * 0.02f) * 50.0f;
                    if (kt == qt) {
                        const int rr = acc_row8(wm, mt, g, i);
                        const int cl = acc_col8(wn, nt, c, i);
                        if (cl > rr) v = -1e30f;
                    }
                    acc[mt][nt][i] = v;
                    pmax[mt][i >> 1] = fmaxf(pmax[mt][i >> 1], v);
                }
        #pragma unroll
        for (int mt = 0; mt < 2; mt++)
            #pragma unroll
            for (int rh = 0; rh < 2; rh++) {
                float p = pmax[mt][rh];
                p = fmaxf(p, __shfl_xor_sync(0xffffffffu, p, 1));
                p = fmaxf(p, __shfl_xor_sync(0xffffffffu, p, 2));
                pmax[mt][rh] = p;
            }
        if (c == 0) {
            #pragma unroll
            for (int mt = 0; mt < 2; mt++)
                #pragma unroll
                for (int rh = 0; rh < 2; rh++)
                    rmax[wn * 128 + m0b + mt * 16 + rh * 8 + g] = pmax[mt][rh];
        }
        __syncthreads();

        float mnew[2][2], scal[2][2], psum[2][2] = {};
        #pragma unroll
        for (int mt = 0; mt < 2; mt++)
            #pragma unroll
            for (int rh = 0; rh < 2; rh++) {
                const int rr = m0b + mt * 16 + rh * 8 + g;
                const float mo = m_state[rr];
                const float tm = fmaxf(rmax[rr], rmax[128 + rr]);
                const float mn = fmaxf(mo, tm);
                mnew[mt][rh] = mn;
                scal[mt][rh] = __expf(mo - mn);
            }
        #pragma unroll
        for (int mt = 0; mt < 2; mt++)
            #pragma unroll
            for (int nt = 0; nt < 8; nt++)
                #pragma unroll
                for (int i = 0; i < 4; i++) {
                    const int rr = acc_row8(wm, mt, g, i);
                    const int cl = acc_col8(wn, nt, c, i);
                    const float p = __expf(acc[mt][nt][i] - mnew[mt][i >> 1]);
                    psum[mt][i >> 1] += p;
                    Ps[rr * QLD + cl] = f2tf(p);
                }
        #pragma unroll
        for (int mt = 0; mt < 2; mt++)
            #pragma unroll
            for (int rh = 0; rh < 2; rh++) {
                float p = psum[mt][rh];
                p += __shfl_xor_sync(0xffffffffu, p, 1);
                p += __shfl_xor_sync(0xffffffffu, p, 2);
                psum[mt][rh] = p;
            }
        if (c == 0) {
            #pragma unroll
            for (int mt = 0; mt < 2; mt++)
                #pragma unroll
                for (int rh = 0; rh < 2; rh++)
                    rsum[wn * 128 + m0b + mt * 16 + rh * 8 + g] = psum[mt][rh];
        }
        __syncthreads();

        if (wn == 0 && c == 0) {
            #pragma unroll
            for (int mt = 0; mt < 2; mt++)
                #pragma unroll
                for (int rh = 0; rh < 2; rh++) {
                    const int rr = m0b + mt * 16 + rh * 8 + g;
                    l_state[rr] = l_state[rr] * scal[mt][rh] + rsum[rr] + rsum[128 + rr];
                    m_state[rr] = mnew[mt][rh];
                }
        }
        #pragma unroll
        for (int mt = 0; mt < 2; mt++)
            #pragma unroll
            for (int nt = 0; nt < 8; nt++)
                #pragma unroll
                for (int i = 0; i < 4; i++)
                    acc_o[mt][nt][i] *= scal[mt][i >> 1];

        #pragma unroll
        for (int s = 0; s < 16; s++) {
            const int idx = s * 256 + tid;
            const int row = idx >> 5;
            const int cf  = (idx & 31) << 2;
            cp16(kvb + (row * VLD + cf) * 4, &Vg[(size_t)row * DHEAD + cf]);
        }
        cp_commit();
        cp_wait<0>();
        __syncthreads();

        #pragma unroll
        for (int kk = 0; kk < 128; kk += 8) {
            uint32_t af[2][4];
            #pragma unroll
            for (int mt = 0; mt < 2; mt++) {
                const int m0 = m0b + mt * 16 + g;
                const float2 p0 = *reinterpret_cast<const float2*>(&Ps[m0 * QLD + kk + 2 * c]);
                const float2 p1 = *reinterpret_cast<const float2*>(&Ps[(m0 + 8) * QLD + kk + 2 * c]);
                af[mt][0] = __float_as_uint(p0.x); af[mt][2] = __float_as_uint(p0.y);
                af[mt][1] = __float_as_uint(p1.x); af[mt][3] = __float_as_uint(p1.y);
            }
            #pragma unroll
            for (int nt = 0; nt < 8; nt++) {
                const int n0 = wn * 64 + nt * 8 + g;
                const uint32_t b0 = __float_as_uint(KV[(kk + 2 * c) * VLD + n0]);
                const uint32_t b1 = __float_as_uint(KV[(kk + 2 * c + 1) * VLD + n0]);
                #pragma unroll
                for (int mt = 0; mt < 2; mt++)
                    mma_tf32(acc_o[mt][nt], af[mt], b0, b1);
            }
        }
    }

    float inv[2][2];
    #pragma unroll
    for (int mt = 0; mt < 2; mt++)
        #pragma unroll
        for (int rh = 0; rh < 2; rh++)
            inv[mt][rh] = 1.0f / l_state[m0b + mt * 16 + rh * 8 + g];
    #pragma unroll
    for (int mt = 0; mt < 2; mt++)
        #pragma unroll
        for (int nt = 0; nt < 8; nt++)
            #pragma unroll
            for (int i = 0; i < 4; i++) {
                const int q  = rb + acc_row8(wm, mt, g, i);
                const int dh = acc_col8(wn, nt, c, i);
                g_attn[(size_t)q * DMODEL + h * DHEAD + dh] =
                    f2tf(acc_o[mt][nt][i] * inv[mt][i >> 1]);
            }
}

// ---------------- kernel 4: output projection -------------------------------
__global__ __launch_bounds__(256, 1) void oproj_kernel(const float* __restrict__ wo,
                                                       float* __restrict__ out) {
    extern __shared__ float dsm[];
    const int rb = blockIdx.x * 256, cb = blockIdx.y * 128;
    float acc[4][8][4] = {};
    gemm256(g_attn + (size_t)rb * DMODEL, DMODEL,
            wo + (size_t)cb * DMODEL, DMODEL, acc, dsm);

    const int tid = threadIdx.x, warp = tid >> 5, lane = tid & 31;
    const int wm = warp >> 1, wn = warp & 1, g = lane >> 2, c = lane & 3;
    #pragma unroll
    for (int mt = 0; mt < 4; mt++)
        #pragma unroll
        for (int nt = 0; nt < 8; nt++)
            #pragma unroll
            for (int i = 0; i < 4; i++) {
                const int s = rb + wm * 64 + mt * 16 + g + ((i >> 1) << 3);
                const int d = cb + wn * 64 + nt * 8 + c * 2 + (i & 1);
                out[(size_t)s * DMODEL + d] = acc[mt][nt][i];
            }
}

// ---------------- launch ----------------------------------------------------
extern "C" void kernel_launch(void* const* d_in, const int* in_sizes, int n_in,
                              void* d_out, int out_size) {
    (void)in_sizes; (void)n_in; (void)out_size;
    const float* x  = (const float*)d_in[0];
    const float* rc = (const float*)d_in[1];
    const float* rs = (const float*)d_in[2];
    const float* wq = (const float*)d_in[4];
    const float* wk = (const float*)d_in[5];
    const float* wv = (const float*)d_in[6];
    const float* wo = (const float*)d_in[7];
    float* out = (float*)d_out;

    const int dense_smem = DSM_TOT * (int)sizeof(float);   // 184320 B
    const int flash_smem = FL_TOT * (int)sizeof(float);    // ~212 KB
    cudaFuncSetAttribute(flash_kernel,
                         cudaFuncAttributeMaxDynamicSharedMemorySize, flash_smem);
    cudaFuncSetAttribute(qkv_kernel,
                         cudaFuncAttributeMaxDynamicSharedMemorySize, dense_smem);
    cudaFuncSetAttribute(oproj_kernel,
                         cudaFuncAttributeMaxDynamicSharedMemorySize, dense_smem);

    qkv_kernel<<<dim3(8, 16, 3), 256, dense_smem>>>(x, wq, wk, wv);
    rope_kernel<<<16384, 256>>>(rc, rs);
    flash_kernel<<<256, 256, flash_smem>>>();
    oproj_kernel<<<dim3(8, 16), 256, dense_smem>>>(wo, out);
}